// round 1
// baseline (speedup 1.0000x reference)
#include <cuda_runtime.h>
#include <math.h>
#include <stdint.h>

#define SEQ   512
#define BATCH 64
#define INDIM 128
#define HDIM  512
#define CLUSTER_G 8      // CTAs per cluster (each owns 64 h-columns)
#define BT        4      // batch elements per cluster
#define JC        64     // output columns per CTA
#define NTHREADS  512
#define NWARPS    16
#define WH_STRIDE 66     // padded row stride (floats), even for float2 alignment
#define WI_STRIDE 66

// SMEM layout (floats)
#define WH_FLOATS   (HDIM * WH_STRIDE)          // 512*66 = 33792
#define WI_FLOATS   (INDIM * WI_STRIDE)         // 128*66 = 8448
#define HT_FLOATS   (2 * HDIM * BT)             // double buffered hT[buf][k][b] = 4096
#define XT_FLOATS   (2 * INDIM * BT)            // double buffered xT[buf][k][b] = 1024
#define PART_FLOATS (NWARPS * BT * JC)          // 16*256 = 4096
#define BIAS_FLOATS (JC)
#define SMEM_FLOATS (WH_FLOATS + WI_FLOATS + HT_FLOATS + XT_FLOATS + PART_FLOATS + BIAS_FLOATS)
#define SMEM_BYTES  (SMEM_FLOATS * 4)           // 206,848 B < 227 KB

__device__ __forceinline__ void cluster_sync_all() {
    asm volatile("barrier.cluster.arrive.aligned;" ::: "memory");
    asm volatile("barrier.cluster.wait.aligned;" ::: "memory");
}

__device__ __forceinline__ uint32_t smem_u32(const void* p) {
    return (uint32_t)__cvta_generic_to_shared(p);
}

__device__ __forceinline__ void st_peer_f32(uint32_t laddr, uint32_t peer, float v) {
    uint32_t r;
    asm volatile("mapa.shared::cluster.u32 %0, %1, %2;" : "=r"(r) : "r"(laddr), "r"(peer));
    asm volatile("st.shared::cluster.f32 [%0], %1;" :: "r"(r), "f"(v) : "memory");
}

__global__ void __cluster_dims__(CLUSTER_G, 1, 1) __launch_bounds__(NTHREADS, 1)
rnn_persistent_kernel(const float* __restrict__ x,
                      const float* __restrict__ Wi,
                      const float* __restrict__ bi,
                      const float* __restrict__ Wh,
                      const float* __restrict__ bh,
                      float* __restrict__ out)
{
    extern __shared__ float smem[];
    float* WhT  = smem;                       // [k][jl] stride WH_STRIDE
    float* WiT  = WhT + WH_FLOATS;            // [k][jl] stride WI_STRIDE
    float* hT   = WiT + WI_FLOATS;            // [buf][k 0..511][b 0..3]
    float* xT   = hT  + HT_FLOATS;            // [buf][k 0..127][b 0..3]
    float* part = xT  + XT_FLOATS;            // [w][b][jl]
    float* bias = part + PART_FLOATS;         // [jl]

    const int tid  = threadIdx.x;
    const int rank = blockIdx.x & (CLUSTER_G - 1);
    const int cl   = blockIdx.x >> 3;
    const int b0   = cl * BT;                 // global batch base for this cluster
    const int j0   = rank * JC;               // global h-column base for this CTA

    // ---- init: load weight shards (transposed, padded), bias, zero h0, load x[0]
    for (int i = tid; i < JC * HDIM; i += NTHREADS) {
        int jl = i >> 9;            // i / 512
        int k  = i & (HDIM - 1);
        WhT[k * WH_STRIDE + jl] = Wh[(j0 + jl) * HDIM + k];
    }
    for (int i = tid; i < JC * INDIM; i += NTHREADS) {
        int jl = i >> 7;
        int k  = i & (INDIM - 1);
        WiT[k * WI_STRIDE + jl] = Wi[(j0 + jl) * INDIM + k];
    }
    if (tid < JC) bias[tid] = bi[j0 + tid] + bh[j0 + tid];
    for (int i = tid; i < HDIM * BT; i += NTHREADS) hT[i] = 0.0f;   // buffer 0 = h(-1) = 0
    for (int i = tid; i < INDIM * BT; i += NTHREADS) {
        int b = i >> 7;
        int k = i & (INDIM - 1);
        xT[k * BT + b] = x[(size_t)0 * BATCH * INDIM + (b0 + b) * INDIM + k];
    }
    __syncthreads();

    const int warp = tid >> 5;
    const int lane = tid & 31;
    const int j2   = lane << 1;               // lane owns columns j2, j2+1
    const int pb   = tid >> 7;                // prefetch mapping: b
    const int pk   = tid & (INDIM - 1);       // prefetch mapping: k

    const uint32_t hT_base = smem_u32(hT);

    for (int t = 0; t < SEQ; t++) {
        const int cur = t & 1;
        const int nxt = cur ^ 1;
        const float* hcur = hT + cur * (HDIM * BT);
        const float* xcur = xT + cur * (INDIM * BT);

        // prefetch x[t+1] (one element per thread), store to back buffer later
        float xv = 0.0f;
        if (t + 1 < SEQ)
            xv = x[(size_t)(t + 1) * BATCH * INDIM + (b0 + pb) * INDIM + pk];

        // ---- K-split GEMM: this warp covers recurrent k in [32w,32w+32), xi k in [8w,8w+8)
        float a00 = 0.f, a01 = 0.f, a10 = 0.f, a11 = 0.f;
        float a20 = 0.f, a21 = 0.f, a30 = 0.f, a31 = 0.f;

        {
            const float*  hp = hcur + (warp << 5) * BT;
            const float*  wp = WhT + (warp << 5) * WH_STRIDE + j2;
            #pragma unroll 8
            for (int kk = 0; kk < 32; kk++) {
                const float4 h4 = *reinterpret_cast<const float4*>(hp + (kk << 2));
                const float2 w2 = *reinterpret_cast<const float2*>(wp + kk * WH_STRIDE);
                a00 = fmaf(h4.x, w2.x, a00); a01 = fmaf(h4.x, w2.y, a01);
                a10 = fmaf(h4.y, w2.x, a10); a11 = fmaf(h4.y, w2.y, a11);
                a20 = fmaf(h4.z, w2.x, a20); a21 = fmaf(h4.z, w2.y, a21);
                a30 = fmaf(h4.w, w2.x, a30); a31 = fmaf(h4.w, w2.y, a31);
            }
        }
        {
            const float*  xp = xcur + (warp << 3) * BT;
            const float*  wp = WiT + (warp << 3) * WI_STRIDE + j2;
            #pragma unroll
            for (int kk = 0; kk < 8; kk++) {
                const float4 h4 = *reinterpret_cast<const float4*>(xp + (kk << 2));
                const float2 w2 = *reinterpret_cast<const float2*>(wp + kk * WI_STRIDE);
                a00 = fmaf(h4.x, w2.x, a00); a01 = fmaf(h4.x, w2.y, a01);
                a10 = fmaf(h4.y, w2.x, a10); a11 = fmaf(h4.y, w2.y, a11);
                a20 = fmaf(h4.z, w2.x, a20); a21 = fmaf(h4.z, w2.y, a21);
                a30 = fmaf(h4.w, w2.x, a30); a31 = fmaf(h4.w, w2.y, a31);
            }
        }

        // store partials: part[w][b][jl]
        {
            float* pp = part + warp * (BT * JC) + j2;
            *reinterpret_cast<float2*>(pp + 0 * JC) = make_float2(a00, a01);
            *reinterpret_cast<float2*>(pp + 1 * JC) = make_float2(a10, a11);
            *reinterpret_cast<float2*>(pp + 2 * JC) = make_float2(a20, a21);
            *reinterpret_cast<float2*>(pp + 3 * JC) = make_float2(a30, a31);
        }

        // store prefetched x into back buffer (read only after next cluster sync)
        xT[nxt * (INDIM * BT) + pk * BT + pb] = xv;

        __syncthreads();

        // ---- reduce across 16 warps, bias + tanh, write out + broadcast to cluster
        if (tid < BT * JC) {
            const int b  = tid >> 6;
            const int jl = tid & (JC - 1);
            float s = 0.0f;
            #pragma unroll
            for (int w = 0; w < NWARPS; w++)
                s += part[w * (BT * JC) + b * JC + jl];
            const float v = tanhf(s + bias[jl]);

            // global h_seq
            out[(size_t)t * BATCH * HDIM + (b0 + b) * HDIM + (j0 + jl)] = v;
            if (t == SEQ - 1)
                out[(size_t)SEQ * BATCH * HDIM + (b0 + b) * HDIM + (j0 + jl)] = v;

            // push into every cluster CTA's back h buffer (including own, via mapa)
            const uint32_t laddr =
                hT_base + (uint32_t)((nxt * (HDIM * BT) + (j0 + jl) * BT + b) * 4);
            #pragma unroll
            for (int p = 0; p < CLUSTER_G; p++)
                st_peer_f32(laddr, (uint32_t)p, v);
        }

        cluster_sync_all();   // release: all pushes visible; full cluster step barrier
    }
}

extern "C" void kernel_launch(void* const* d_in, const int* in_sizes, int n_in,
                              void* d_out, int out_size) {
    const float* x  = (const float*)d_in[0];
    const float* Wi = (const float*)d_in[1];
    const float* bi = (const float*)d_in[2];
    const float* Wh = (const float*)d_in[3];
    const float* bh = (const float*)d_in[4];
    float* out = (float*)d_out;

    cudaFuncSetAttribute(rnn_persistent_kernel,
                         cudaFuncAttributeMaxDynamicSharedMemorySize, SMEM_BYTES);

    // 16 clusters x 8 CTAs = 128 CTAs (1 per SM), 512 threads each
    rnn_persistent_kernel<<<(BATCH / BT) * CLUSTER_G, NTHREADS, SMEM_BYTES>>>(
        x, Wi, bi, Wh, bh, out);
}

// round 2
// speedup vs baseline: 1.8034x; 1.8034x over previous
#include <cuda_runtime.h>
#include <math.h>
#include <stdint.h>

#define SEQ   512
#define BATCH 64
#define INDIM 128
#define HDIM  512
#define CLUSTER_G 8
#define BT        4
#define JC        64
#define NTHREADS  512
#define NWARPS    16
#define WH_STRIDE 66
#define WI_STRIDE 66

#define WH_FLOATS   (HDIM * WH_STRIDE)          // 33792
#define WI_FLOATS   (INDIM * WI_STRIDE)         // 8448
#define HT_HALF     (HDIM * BT)                 // 2048 floats per buffer
#define HT_FLOATS   (2 * HT_HALF)               // 4096
#define XT_HALF     (INDIM * BT)                // 512
#define XT_FLOATS   (2 * XT_HALF)               // 1024
#define PART_FLOATS (NWARPS * BT * JC)          // 4096  layout [w][jl][b]
#define BIAS_FLOATS (JC)
#define STAGE_FLOATS (BT * JC)                  // 256   layout [jl][b]
#define BAR_FLOATS  16
#define SMEM_FLOATS (WH_FLOATS + WI_FLOATS + HT_FLOATS + XT_FLOATS + PART_FLOATS + BIAS_FLOATS + STAGE_FLOATS + BAR_FLOATS)
#define SMEM_BYTES  (SMEM_FLOATS * 4)           // ~207,232 B

__device__ __forceinline__ void cluster_sync_all() {
    asm volatile("barrier.cluster.arrive.aligned;" ::: "memory");
    asm volatile("barrier.cluster.wait.aligned;" ::: "memory");
}
__device__ __forceinline__ uint32_t smem_u32(const void* p) {
    return (uint32_t)__cvta_generic_to_shared(p);
}
__device__ __forceinline__ void mbar_init(uint32_t a, uint32_t cnt) {
    asm volatile("mbarrier.init.shared.b64 [%0], %1;" :: "r"(a), "r"(cnt) : "memory");
}
__device__ __forceinline__ void mbar_arrive_expect_tx(uint32_t a, uint32_t tx) {
    asm volatile("mbarrier.arrive.expect_tx.shared.b64 _, [%0], %1;" :: "r"(a), "r"(tx) : "memory");
}
__device__ __forceinline__ void mbar_remote_arrive(uint32_t a, uint32_t rank) {
    asm volatile(
        "{\n\t.reg .b32 ra;\n\t"
        "mapa.shared::cluster.u32 ra, %0, %1;\n\t"
        "mbarrier.arrive.shared::cluster.b64 _, [ra];\n\t}"
        :: "r"(a), "r"(rank) : "memory");
}
__device__ __forceinline__ void mbar_wait_parity(uint32_t a, uint32_t ph) {
    asm volatile(
        "{\n\t.reg .pred P;\n"
        "W_%=:\n\t"
        "mbarrier.try_wait.parity.acquire.cta.shared::cta.b64 P, [%0], %1, 0x989680;\n\t"
        "@P bra D_%=;\n\t"
        "bra W_%=;\n"
        "D_%=:\n\t}"
        :: "r"(a), "r"(ph) : "memory");
}
__device__ __forceinline__ void bulk_copy_to_peer(uint32_t dst_local, uint32_t src,
                                                  uint32_t bytes, uint32_t mbar_local,
                                                  uint32_t rank) {
    asm volatile(
        "{\n\t.reg .b32 rd, rb;\n\t"
        "mapa.shared::cluster.u32 rd, %0, %4;\n\t"
        "mapa.shared::cluster.u32 rb, %3, %4;\n\t"
        "cp.async.bulk.shared::cluster.shared::cta.mbarrier::complete_tx::bytes [rd], [%1], %2, [rb];\n\t}"
        :: "r"(dst_local), "r"(src), "r"(bytes), "r"(mbar_local), "r"(rank) : "memory");
}
__device__ __forceinline__ long long fma2(long long a, long long b, long long c) {
    long long d;
    asm("fma.rn.f32x2 %0, %1, %2, %3;" : "=l"(d) : "l"(a), "l"(b), "l"(c));
    return d;
}
__device__ __forceinline__ long long pack2(float x) {
    long long d;
    asm("mov.b64 %0, {%1, %1};" : "=l"(d) : "f"(x));
    return d;
}

__global__ void __cluster_dims__(CLUSTER_G, 1, 1) __launch_bounds__(NTHREADS, 1)
rnn_persistent_kernel(const float* __restrict__ x,
                      const float* __restrict__ Wi,
                      const float* __restrict__ bi,
                      const float* __restrict__ Wh,
                      const float* __restrict__ bh,
                      float* __restrict__ out)
{
    extern __shared__ float smem[];
    float* WhT   = smem;                       // [k][jl] stride 66
    float* WiT   = WhT + WH_FLOATS;
    float* hT    = WiT + WI_FLOATS;            // [buf][k][b]
    float* xT    = hT  + HT_FLOATS;            // [buf][k][b]
    float* part  = xT  + XT_FLOATS;            // [w][jl][b]
    float* bias  = part + PART_FLOATS;
    float* stage = bias + BIAS_FLOATS;         // [jl][b] — matches hT slice layout
    unsigned long long* bars = (unsigned long long*)(stage + STAGE_FLOATS);
    // bars[0]=full0 bars[1]=full1 bars[2]=empty0 bars[3]=empty1

    const int tid  = threadIdx.x;
    const int rank = blockIdx.x & (CLUSTER_G - 1);
    const int cl   = blockIdx.x >> 3;
    const int b0   = cl * BT;
    const int j0   = rank * JC;

    const uint32_t hT_base    = smem_u32(hT);
    const uint32_t stage_base = smem_u32(stage);
    const uint32_t full_bar0  = smem_u32(&bars[0]);
    const uint32_t empty_bar0 = smem_u32(&bars[2]);

    // ---- init weights/bias/h0/x0
    for (int i = tid; i < JC * HDIM; i += NTHREADS) {
        int jl = i >> 9;
        int k  = i & (HDIM - 1);
        WhT[k * WH_STRIDE + jl] = Wh[(j0 + jl) * HDIM + k];
    }
    for (int i = tid; i < JC * INDIM; i += NTHREADS) {
        int jl = i >> 7;
        int k  = i & (INDIM - 1);
        WiT[k * WI_STRIDE + jl] = Wi[(j0 + jl) * INDIM + k];
    }
    if (tid < JC) bias[tid] = bi[j0 + tid] + bh[j0 + tid];
    for (int i = tid; i < HT_HALF; i += NTHREADS) hT[i] = 0.0f;
    for (int i = tid; i < XT_HALF; i += NTHREADS) {
        int b = i >> 7;
        int k = i & (INDIM - 1);
        xT[k * BT + b] = x[(size_t)(b0 + b) * INDIM + k];
    }
    if (tid == 0) {
        mbar_init(full_bar0 + 0, 1);   // full[0]
        mbar_init(full_bar0 + 8, 1);   // full[1]
        mbar_init(empty_bar0 + 0, 8);  // empty[0]
        mbar_init(empty_bar0 + 8, 8);  // empty[1]
        // arm full barriers for their first phase (expect 8x1KB)
        mbar_arrive_expect_tx(full_bar0 + 0, 8192);
        mbar_arrive_expect_tx(full_bar0 + 8, 8192);
    }
    __syncthreads();
    cluster_sync_all();                 // barriers + weights visible cluster-wide
    if (tid == 0) {                     // pre-release empty[1] (first producer target)
        #pragma unroll
        for (int p = 0; p < CLUSTER_G; p++) mbar_remote_arrive(empty_bar0 + 8, (uint32_t)p);
    }

    const int warp = tid >> 5;
    const int lane = tid & 31;
    const int j2   = lane << 1;
    const int pb   = tid >> 7;
    const int pk   = tid & (INDIM - 1);

    for (int t = 0; t < SEQ; t++) {
        const int cur = t & 1;
        const int nxt = cur ^ 1;

        if (t > 0) {
            mbar_wait_parity(full_bar0 + cur * 8, (uint32_t)(((t - 1) >> 1) & 1));
            if (tid == 0) mbar_arrive_expect_tx(full_bar0 + cur * 8, 8192);  // re-arm next phase
        }

        const float* hcur = hT + cur * HT_HALF;
        const float* xcur = xT + cur * XT_HALF;

        float xv = 0.0f;
        if (t + 1 < SEQ)
            xv = x[(size_t)(t + 1) * BATCH * INDIM + (b0 + pb) * INDIM + pk];

        // ---- K-split GEMM with packed f32x2 accumulators (b-pairs)
        long long a0 = 0, a1 = 0, a2 = 0, a3 = 0;
        {
            const float* hp = hcur + (warp << 5) * BT;
            const float* wp = WhT + (warp << 5) * WH_STRIDE + j2;
            #pragma unroll 8
            for (int kk = 0; kk < 32; kk++) {
                const double2 hd = *reinterpret_cast<const double2*>(hp + (kk << 2));
                const long long hlo = __double_as_longlong(hd.x);   // (h[b0],h[b1])
                const long long hhi = __double_as_longlong(hd.y);   // (h[b2],h[b3])
                const float2 w2 = *reinterpret_cast<const float2*>(wp + kk * WH_STRIDE);
                const long long wx = pack2(w2.x);
                const long long wy = pack2(w2.y);
                a0 = fma2(hlo, wx, a0); a1 = fma2(hhi, wx, a1);
                a2 = fma2(hlo, wy, a2); a3 = fma2(hhi, wy, a3);
            }
        }
        {
            const float* xp = xcur + (warp << 3) * BT;
            const float* wp = WiT + (warp << 3) * WI_STRIDE + j2;
            #pragma unroll
            for (int kk = 0; kk < 8; kk++) {
                const double2 hd = *reinterpret_cast<const double2*>(xp + (kk << 2));
                const long long hlo = __double_as_longlong(hd.x);
                const long long hhi = __double_as_longlong(hd.y);
                const float2 w2 = *reinterpret_cast<const float2*>(wp + kk * WI_STRIDE);
                const long long wx = pack2(w2.x);
                const long long wy = pack2(w2.y);
                a0 = fma2(hlo, wx, a0); a1 = fma2(hhi, wx, a1);
                a2 = fma2(hlo, wy, a2); a3 = fma2(hhi, wy, a3);
            }
        }

        // partials: part[w][jl][b] — (a0,a1) -> jl=j2, (a2,a3) -> jl=j2+1
        {
            float* pp = part + warp * (BT * JC) + (j2 << 2);
            *reinterpret_cast<ulonglong2*>(pp + 0) =
                make_ulonglong2((unsigned long long)a0, (unsigned long long)a1);
            *reinterpret_cast<ulonglong2*>(pp + 4) =
                make_ulonglong2((unsigned long long)a2, (unsigned long long)a3);
        }

        xT[nxt * XT_HALF + pk * BT + pb] = xv;

        __syncthreads();   // partials + xT visible; all reads of hT[cur] done

        if (tid == 0) {    // release hT[cur] for refill (step t+1 producers)
            #pragma unroll
            for (int p = 0; p < CLUSTER_G; p++)
                mbar_remote_arrive(empty_bar0 + cur * 8, (uint32_t)p);
        }

        if (tid < BT * JC) {
            const int b  = tid & 3;
            const int jl = tid >> 2;
            float s = 0.0f;
            #pragma unroll
            for (int w = 0; w < NWARPS; w++)
                s += part[w * (BT * JC) + tid];
            const float v = tanhf(s + bias[jl]);

            out[(size_t)t * BATCH * HDIM + (b0 + b) * HDIM + (j0 + jl)] = v;
            if (t == SEQ - 1)
                out[(size_t)SEQ * BATCH * HDIM + (b0 + b) * HDIM + (j0 + jl)] = v;

            stage[tid] = v;             // [jl][b] contiguous 1KB slice
        }

        __syncthreads();   // stage complete

        if (t + 1 < SEQ && tid == 0) {
            asm volatile("fence.proxy.async.shared::cta;" ::: "memory");
            mbar_wait_parity(empty_bar0 + nxt * 8, (uint32_t)((t >> 1) & 1));
            const uint32_t dst = hT_base + (uint32_t)(nxt * HT_HALF * 4 + j0 * BT * 4);
            #pragma unroll
            for (int p = 0; p < CLUSTER_G; p++)
                bulk_copy_to_peer(dst, stage_base, (uint32_t)(BT * JC * 4),
                                  full_bar0 + nxt * 8, (uint32_t)p);
        }
    }

    cluster_sync_all();   // no CTA exits while peers' DSMEM ops may be in flight
}

extern "C" void kernel_launch(void* const* d_in, const int* in_sizes, int n_in,
                              void* d_out, int out_size) {
    const float* x  = (const float*)d_in[0];
    const float* Wi = (const float*)d_in[1];
    const float* bi = (const float*)d_in[2];
    const float* Wh = (const float*)d_in[3];
    const float* bh = (const float*)d_in[4];
    float* out = (float*)d_out;

    cudaFuncSetAttribute(rnn_persistent_kernel,
                         cudaFuncAttributeMaxDynamicSharedMemorySize, SMEM_BYTES);

    rnn_persistent_kernel<<<(BATCH / BT) * CLUSTER_G, NTHREADS, SMEM_BYTES>>>(
        x, Wi, bi, Wh, bh, out);
}

// round 3
// speedup vs baseline: 2.0432x; 1.1329x over previous
#include <cuda_runtime.h>
#include <math.h>
#include <stdint.h>

#define SEQ   512
#define BATCH 64
#define INDIM 128
#define HDIM  512
#define CLUSTER_G 8
#define BT        4
#define JC        64
#define NTHREADS  512
#define NWARPS    16
#define KWH       32            // Wh k-range per warp
#define KWI       8             // Wi k-range per warp
#define WIT_STRIDE 66

// SMEM byte offsets
#define OFF_WIT   0                                  // float[128][66]
#define OFF_BIAS  (OFF_WIT + 128*WIT_STRIDE*4)       // 33792
#define OFF_HDUP  (OFF_BIAS + 256)                   // 34048  float2[2][512][4]
#define OFF_XDUP  (OFF_HDUP + 2*HDIM*BT*8)           // 66816  float2[2][128][4]
#define OFF_PART  (OFF_XDUP + 2*INDIM*BT*8)          // 75008  float[16][4][64]
#define OFF_STAGE (OFF_PART + NWARPS*BT*JC*4)        // 91392  float2[64][4]
#define OFF_BARS  (OFF_STAGE + JC*BT*8)              // 93440  4 x u64
#define OFF_WTMP  (OFF_BARS + 64)                    // 93504  float[64][512] (init only)
#define SMEM_BYTES (OFF_WTMP + JC*HDIM*4)            // 224576

__device__ __forceinline__ void cluster_sync_all() {
    asm volatile("barrier.cluster.arrive.aligned;" ::: "memory");
    asm volatile("barrier.cluster.wait.aligned;" ::: "memory");
}
__device__ __forceinline__ uint32_t smem_u32(const void* p) {
    return (uint32_t)__cvta_generic_to_shared(p);
}
__device__ __forceinline__ void mbar_init(uint32_t a, uint32_t cnt) {
    asm volatile("mbarrier.init.shared.b64 [%0], %1;" :: "r"(a), "r"(cnt) : "memory");
}
__device__ __forceinline__ void mbar_arrive_expect_tx(uint32_t a, uint32_t tx) {
    asm volatile("mbarrier.arrive.expect_tx.shared.b64 _, [%0], %1;" :: "r"(a), "r"(tx) : "memory");
}
__device__ __forceinline__ void mbar_remote_arrive(uint32_t a, uint32_t rank) {
    asm volatile(
        "{\n\t.reg .b32 ra;\n\t"
        "mapa.shared::cluster.u32 ra, %0, %1;\n\t"
        "mbarrier.arrive.shared::cluster.b64 _, [ra];\n\t}"
        :: "r"(a), "r"(rank) : "memory");
}
__device__ __forceinline__ void mbar_wait_parity(uint32_t a, uint32_t ph) {
    asm volatile(
        "{\n\t.reg .pred P;\n"
        "W_%=:\n\t"
        "mbarrier.try_wait.parity.acquire.cta.shared::cta.b64 P, [%0], %1, 0x989680;\n\t"
        "@P bra D_%=;\n\t"
        "bra W_%=;\n"
        "D_%=:\n\t}"
        :: "r"(a), "r"(ph) : "memory");
}
__device__ __forceinline__ void bulk_copy_to_peer(uint32_t dst_local, uint32_t src,
                                                  uint32_t bytes, uint32_t mbar_local,
                                                  uint32_t rank) {
    asm volatile(
        "{\n\t.reg .b32 rd, rb;\n\t"
        "mapa.shared::cluster.u32 rd, %0, %4;\n\t"
        "mapa.shared::cluster.u32 rb, %3, %4;\n\t"
        "cp.async.bulk.shared::cluster.shared::cta.mbarrier::complete_tx::bytes [rd], [%1], %2, [rb];\n\t}"
        :: "r"(dst_local), "r"(src), "r"(bytes), "r"(mbar_local), "r"(rank) : "memory");
}
__device__ __forceinline__ long long fma2(long long a, long long b, long long c) {
    long long d;
    asm("fma.rn.f32x2 %0, %1, %2, %3;" : "=l"(d) : "l"(a), "l"(b), "l"(c));
    return d;
}
__device__ __forceinline__ long long packxy(float x, float y) {
    long long d;
    asm("mov.b64 %0, {%1, %2};" : "=l"(d) : "f"(x), "f"(y));
    return d;
}

__global__ void __cluster_dims__(CLUSTER_G, 1, 1) __launch_bounds__(NTHREADS, 1)
rnn_persistent_kernel(const float* __restrict__ x,
                      const float* __restrict__ Wi,
                      const float* __restrict__ bi,
                      const float* __restrict__ Wh,
                      const float* __restrict__ bh,
                      float* __restrict__ out)
{
    extern __shared__ char smem[];
    float*  WiT   = (float*)(smem + OFF_WIT);
    float*  bias  = (float*)(smem + OFF_BIAS);
    float2* hdup  = (float2*)(smem + OFF_HDUP);   // [buf][k][b] entries (h,h)
    float2* xdup  = (float2*)(smem + OFF_XDUP);   // [buf][k][b]
    float*  part  = (float*)(smem + OFF_PART);    // [w][b][jl]
    float2* stage = (float2*)(smem + OFF_STAGE);  // [jl][b]
    float*  Wtmp  = (float*)(smem + OFF_WTMP);    // [jl][k] init-only

    const int tid  = threadIdx.x;
    const int rank = blockIdx.x & (CLUSTER_G - 1);
    const int cl   = blockIdx.x >> 3;
    const int b0   = cl * BT;
    const int j0   = rank * JC;

    const uint32_t hdup_base  = smem_u32(hdup);
    const uint32_t stage_base = smem_u32(stage);
    const uint32_t full_bar0  = smem_u32(smem + OFF_BARS);
    const uint32_t empty_bar0 = full_bar0 + 16;

    const int warp = tid >> 5;
    const int lane = tid & 31;
    const int j2   = lane << 1;

    // ---- init: stage Wh shard (contiguous copy), WiT, bias, h0, x0
    for (int i = tid; i < JC * HDIM; i += NTHREADS)
        Wtmp[i] = Wh[(size_t)j0 * HDIM + i];               // [jl][k]
    for (int i = tid; i < JC * INDIM; i += NTHREADS) {
        int jl = i >> 7;
        int k  = i & (INDIM - 1);
        WiT[k * WIT_STRIDE + jl] = Wi[(j0 + jl) * INDIM + k];
    }
    if (tid < JC) bias[tid] = bi[j0 + tid] + bh[j0 + tid];
    for (int i = tid; i < HDIM * BT; i += NTHREADS) hdup[i] = make_float2(0.f, 0.f);
    {
        int k = tid >> 2, b = tid & 3;                     // 512 threads = 128k x 4b
        float v = x[(size_t)(b0 + b) * INDIM + k];
        xdup[tid] = make_float2(v, v);                     // xdup[0][k][b]
    }
    if (tid == 0) {
        mbar_init(full_bar0 + 0, 1);
        mbar_init(full_bar0 + 8, 1);
        mbar_init(empty_bar0 + 0, 8);
        mbar_init(empty_bar0 + 8, 8);
        mbar_arrive_expect_tx(full_bar0 + 0, 16384);
        mbar_arrive_expect_tx(full_bar0 + 8, 16384);
    }
    __syncthreads();

    // ---- extract per-thread Wh registers: wh[kk] = (W[j2][k], W[j2+1][k])
    long long wh[KWH];
    {
        const int kb = warp * KWH;
        #pragma unroll
        for (int kk = 0; kk < KWH; kk++)
            wh[kk] = packxy(Wtmp[j2 * HDIM + kb + kk], Wtmp[(j2 + 1) * HDIM + kb + kk]);
    }

    cluster_sync_all();
    if (tid == 0) {    // pre-release empty[1]
        #pragma unroll
        for (int p = 0; p < CLUSTER_G; p++) mbar_remote_arrive(empty_bar0 + 8, (uint32_t)p);
    }

    const int pk = tid >> 2;       // x prefetch: k
    const int pb = tid & 3;        // x prefetch: b

    for (int t = 0; t < SEQ; t++) {
        const int cur = t & 1;
        const int nxt = cur ^ 1;

        // prefetch x[t+1]
        float xv = 0.0f;
        if (t + 1 < SEQ)
            xv = x[(size_t)(t + 1) * BATCH * INDIM + (b0 + pb) * INDIM + pk];

        long long a0 = 0, a1 = 0, a2 = 0, a3 = 0;   // (out_j2, out_j2+1) for b=0..3

        // ---- Wi segment first (independent of the h exchange)
        {
            const float2* xc = xdup + cur * (INDIM * BT) + (warp * KWI) * BT;
            const float*  wp = WiT + (warp * KWI) * WIT_STRIDE + j2;
            #pragma unroll
            for (int kk = 0; kk < KWI; kk++) {
                const long long w = *reinterpret_cast<const long long*>(wp + kk * WIT_STRIDE);
                const longlong2 p01 = *reinterpret_cast<const longlong2*>(xc + kk * BT);
                const longlong2 p23 = *reinterpret_cast<const longlong2*>(xc + kk * BT + 2);
                a0 = fma2(p01.x, w, a0); a1 = fma2(p01.y, w, a1);
                a2 = fma2(p23.x, w, a2); a3 = fma2(p23.y, w, a3);
            }
        }

        // ---- wait for h exchange, then Wh segment from register weights
        if (t > 0) {
            mbar_wait_parity(full_bar0 + cur * 8, (uint32_t)(((t - 1) >> 1) & 1));
            if (tid == 0) mbar_arrive_expect_tx(full_bar0 + cur * 8, 16384);
        }
        {
            const float2* hc = hdup + cur * (HDIM * BT) + (warp * KWH) * BT;
            #pragma unroll
            for (int kk = 0; kk < KWH; kk++) {
                const longlong2 p01 = *reinterpret_cast<const longlong2*>(hc + kk * BT);
                const longlong2 p23 = *reinterpret_cast<const longlong2*>(hc + kk * BT + 2);
                a0 = fma2(p01.x, wh[kk], a0); a1 = fma2(p01.y, wh[kk], a1);
                a2 = fma2(p23.x, wh[kk], a2); a3 = fma2(p23.y, wh[kk], a3);
            }
        }

        // partials: part[w][b][jl]
        {
            float* pp = part + warp * (BT * JC) + j2;
            *reinterpret_cast<long long*>(pp +   0) = a0;
            *reinterpret_cast<long long*>(pp +  64) = a1;
            *reinterpret_cast<long long*>(pp + 128) = a2;
            *reinterpret_cast<long long*>(pp + 192) = a3;
        }

        // store prefetched x (read only after next step's syncthreads)
        xdup[nxt * (INDIM * BT) + tid] = make_float2(xv, xv);

        __syncthreads();   // partials + xdup visible; all hdup[cur] reads done

        if (tid == 0) {    // release hdup[cur] for refill
            #pragma unroll
            for (int p = 0; p < CLUSTER_G; p++)
                mbar_remote_arrive(empty_bar0 + cur * 8, (uint32_t)p);
        }

        if (tid < BT * JC) {
            const int b  = tid >> 6;
            const int jl = tid & (JC - 1);
            float s = 0.0f;
            #pragma unroll
            for (int w = 0; w < NWARPS; w++)
                s += part[w * (BT * JC) + tid];
            const float v = tanhf(s + bias[jl]);

            out[(size_t)t * BATCH * HDIM + (b0 + b) * HDIM + (j0 + jl)] = v;
            if (t == SEQ - 1)
                out[(size_t)SEQ * BATCH * HDIM + (b0 + b) * HDIM + (j0 + jl)] = v;

            stage[jl * BT + b] = make_float2(v, v);   // mirrors hdup [k][b] slice
        }

        __syncthreads();   // stage complete

        if (t + 1 < SEQ && tid == 0) {
            asm volatile("fence.proxy.async.shared::cta;" ::: "memory");
            mbar_wait_parity(empty_bar0 + nxt * 8, (uint32_t)((t >> 1) & 1));
            const uint32_t dst = hdup_base + (uint32_t)((nxt * HDIM * BT + j0 * BT) * 8);
            #pragma unroll
            for (int p = 0; p < CLUSTER_G; p++)
                bulk_copy_to_peer(dst, stage_base, (uint32_t)(JC * BT * 8),
                                  full_bar0 + nxt * 8, (uint32_t)p);
        }
    }

    cluster_sync_all();
}

extern "C" void kernel_launch(void* const* d_in, const int* in_sizes, int n_in,
                              void* d_out, int out_size) {
    const float* x  = (const float*)d_in[0];
    const float* Wi = (const float*)d_in[1];
    const float* bi = (const float*)d_in[2];
    const float* Wh = (const float*)d_in[3];
    const float* bh = (const float*)d_in[4];
    float* out = (float*)d_out;

    cudaFuncSetAttribute(rnn_persistent_kernel,
                         cudaFuncAttributeMaxDynamicSharedMemorySize, SMEM_BYTES);

    rnn_persistent_kernel<<<(BATCH / BT) * CLUSTER_G, NTHREADS, SMEM_BYTES>>>(
        x, Wi, bi, Wh, bh, out);
}

// round 4
// speedup vs baseline: 2.6898x; 1.3165x over previous
#include <cuda_runtime.h>
#include <math.h>
#include <stdint.h>

#define SEQ   512
#define BATCH 64
#define INDIM 128
#define HDIM  512
#define CLUSTER_G 8
#define BT        4
#define JC        64
#define NTHREADS  512
#define NWARPS    16
#define KWH       32
#define KWI       8

// SMEM byte offsets
#define OFF_BIAS  0                              // float[64]
#define OFF_HRAW  256                            // float[2][512][4] = 16384
#define OFF_XRAW  (OFF_HRAW + 16384)             // float[2][128][4] = 4096
#define OFF_PART  (OFF_XRAW + 4096)              // float[16][64][4] = 16384
#define OFF_STAGE (OFF_PART + 16384)             // float[64][4] = 1024
#define OFF_BARS  (OFF_STAGE + 1024)             // 4 x u64
#define OFF_WTMP  (OFF_BARS + 64)                // float[64][512] staging (init only)
#define SMEM_BYTES (OFF_WTMP + JC*HDIM*4)        // 169,344 B

__device__ __forceinline__ void cluster_sync_all() {
    asm volatile("barrier.cluster.arrive.aligned;" ::: "memory");
    asm volatile("barrier.cluster.wait.aligned;" ::: "memory");
}
__device__ __forceinline__ uint32_t smem_u32(const void* p) {
    return (uint32_t)__cvta_generic_to_shared(p);
}
__device__ __forceinline__ void mbar_init(uint32_t a, uint32_t cnt) {
    asm volatile("mbarrier.init.shared.b64 [%0], %1;" :: "r"(a), "r"(cnt) : "memory");
}
__device__ __forceinline__ void mbar_arrive_expect_tx(uint32_t a, uint32_t tx) {
    asm volatile("mbarrier.arrive.expect_tx.shared.b64 _, [%0], %1;" :: "r"(a), "r"(tx) : "memory");
}
__device__ __forceinline__ void mbar_remote_arrive(uint32_t a, uint32_t rank) {
    asm volatile(
        "{\n\t.reg .b32 ra;\n\t"
        "mapa.shared::cluster.u32 ra, %0, %1;\n\t"
        "mbarrier.arrive.shared::cluster.b64 _, [ra];\n\t}"
        :: "r"(a), "r"(rank) : "memory");
}
__device__ __forceinline__ void mbar_wait_parity(uint32_t a, uint32_t ph) {
    asm volatile(
        "{\n\t.reg .pred P;\n"
        "W_%=:\n\t"
        "mbarrier.try_wait.parity.acquire.cta.shared::cta.b64 P, [%0], %1, 0x989680;\n\t"
        "@P bra D_%=;\n\t"
        "bra W_%=;\n"
        "D_%=:\n\t}"
        :: "r"(a), "r"(ph) : "memory");
}
__device__ __forceinline__ void bulk_copy_to_peer(uint32_t dst_local, uint32_t src,
                                                  uint32_t bytes, uint32_t mbar_local,
                                                  uint32_t rank) {
    asm volatile(
        "{\n\t.reg .b32 rd, rb;\n\t"
        "mapa.shared::cluster.u32 rd, %0, %4;\n\t"
        "mapa.shared::cluster.u32 rb, %3, %4;\n\t"
        "cp.async.bulk.shared::cluster.shared::cta.mbarrier::complete_tx::bytes [rd], [%1], %2, [rb];\n\t}"
        :: "r"(dst_local), "r"(src), "r"(bytes), "r"(mbar_local), "r"(rank) : "memory");
}
__device__ __forceinline__ long long fma2(long long a, long long b, long long c) {
    long long d;
    asm("fma.rn.f32x2 %0, %1, %2, %3;" : "=l"(d) : "l"(a), "l"(b), "l"(c));
    return d;
}
__device__ __forceinline__ long long dup2(float x) {
    long long d;
    asm("mov.b64 %0, {%1, %1};" : "=l"(d) : "f"(x));
    return d;
}

__global__ void __cluster_dims__(CLUSTER_G, 1, 1) __launch_bounds__(NTHREADS, 1)
rnn_persistent_kernel(const float* __restrict__ x,
                      const float* __restrict__ Wi,
                      const float* __restrict__ bi,
                      const float* __restrict__ Wh,
                      const float* __restrict__ bh,
                      float* __restrict__ out)
{
    extern __shared__ char smem[];
    float* bias  = (float*)(smem + OFF_BIAS);
    float* hraw  = (float*)(smem + OFF_HRAW);    // [buf][k][b] plain fp32
    float* xraw  = (float*)(smem + OFF_XRAW);    // [buf][k][b]
    float* part  = (float*)(smem + OFF_PART);    // [w][jl][b]
    float* stage = (float*)(smem + OFF_STAGE);   // [jl][b]
    float* Wtmp  = (float*)(smem + OFF_WTMP);    // [jl][k] staging

    const int tid  = threadIdx.x;
    const int rank = blockIdx.x & (CLUSTER_G - 1);
    const int cl   = blockIdx.x >> 3;
    const int b0   = cl * BT;
    const int j0   = rank * JC;

    const uint32_t hraw_base  = smem_u32(hraw);
    const uint32_t stage_base = smem_u32(stage);
    const uint32_t full_bar0  = smem_u32(smem + OFF_BARS);
    const uint32_t empty_bar0 = full_bar0 + 16;

    const int warp = tid >> 5;
    const int lane = tid & 31;
    const int j2   = lane << 1;

    // ---- init: bias, h0, x0, barriers
    if (tid < JC) bias[tid] = bi[j0 + tid] + bh[j0 + tid];
    for (int i = tid; i < HDIM * BT; i += NTHREADS) hraw[i] = 0.0f;
    {
        int k = tid >> 2, b = tid & 3;
        xraw[tid] = x[(size_t)(b0 + b) * INDIM + k];
    }
    if (tid == 0) {
        mbar_init(full_bar0 + 0, 1);
        mbar_init(full_bar0 + 8, 1);
        mbar_init(empty_bar0 + 0, 8);
        mbar_init(empty_bar0 + 8, 8);
        mbar_arrive_expect_tx(full_bar0 + 0, 8192);
        mbar_arrive_expect_tx(full_bar0 + 8, 8192);
    }

    // ---- stage Wh shard -> extract per-thread scalar weights
    __syncthreads();
    for (int i = tid; i < JC * HDIM; i += NTHREADS)
        Wtmp[i] = Wh[(size_t)j0 * HDIM + i];               // [jl][k]
    __syncthreads();
    float wha[KWH], whb[KWH];
    {
        const int kb = warp * KWH;
        #pragma unroll
        for (int kk = 0; kk < KWH; kk++) {
            wha[kk] = Wtmp[j2 * HDIM + kb + kk];
            whb[kk] = Wtmp[(j2 + 1) * HDIM + kb + kk];
        }
    }
    __syncthreads();
    for (int i = tid; i < JC * INDIM; i += NTHREADS)
        Wtmp[i] = Wi[(size_t)j0 * INDIM + i];              // [jl][k]
    __syncthreads();
    float wia[KWI], wib[KWI];
    {
        const int kb = warp * KWI;
        #pragma unroll
        for (int kk = 0; kk < KWI; kk++) {
            wia[kk] = Wtmp[j2 * INDIM + kb + kk];
            wib[kk] = Wtmp[(j2 + 1) * INDIM + kb + kk];
        }
    }
    __syncthreads();

    cluster_sync_all();
    if (tid == 0) {    // pre-release empty[1] (first producer target)
        #pragma unroll
        for (int p = 0; p < CLUSTER_G; p++) mbar_remote_arrive(empty_bar0 + 8, (uint32_t)p);
    }

    const int pk = tid >> 2;
    const int pb = tid & 3;

    for (int t = 0; t < SEQ; t++) {
        const int cur = t & 1;
        const int nxt = cur ^ 1;

        float xv = 0.0f;
        if (t + 1 < SEQ)
            xv = x[(size_t)(t + 1) * BATCH * INDIM + (b0 + pb) * INDIM + pk];

        long long a0 = 0, a1 = 0, a2 = 0, a3 = 0;
        // a0=(j2:b0,b1) a1=(j2:b2,b3) a2=(j2+1:b0,b1) a3=(j2+1:b2,b3)

        // ---- Wi segment (independent of h exchange)
        {
            const float* xc = xraw + cur * (INDIM * BT) + (warp * KWI) * BT;
            #pragma unroll
            for (int kk = 0; kk < KWI; kk++) {
                const longlong2 p = *reinterpret_cast<const longlong2*>(xc + (kk << 2));
                const long long wa = dup2(wia[kk]);
                const long long wb = dup2(wib[kk]);
                a0 = fma2(p.x, wa, a0); a1 = fma2(p.y, wa, a1);
                a2 = fma2(p.x, wb, a2); a3 = fma2(p.y, wb, a3);
            }
        }

        // ---- wait for h, then Wh from register weights
        if (t > 0) {
            mbar_wait_parity(full_bar0 + cur * 8, (uint32_t)(((t - 1) >> 1) & 1));
            if (tid == 0) mbar_arrive_expect_tx(full_bar0 + cur * 8, 8192);
        }
        {
            const float* hc = hraw + cur * (HDIM * BT) + (warp * KWH) * BT;
            #pragma unroll
            for (int kk = 0; kk < KWH; kk++) {
                const longlong2 p = *reinterpret_cast<const longlong2*>(hc + (kk << 2));
                const long long wa = dup2(wha[kk]);
                const long long wb = dup2(whb[kk]);
                a0 = fma2(p.x, wa, a0); a1 = fma2(p.y, wa, a1);
                a2 = fma2(p.x, wb, a2); a3 = fma2(p.y, wb, a3);
            }
        }

        // partials: part[w][jl][b] — two contiguous 16B rows
        {
            float* pp = part + warp * (BT * JC) + (j2 << 2);
            *reinterpret_cast<ulonglong2*>(pp + 0) =
                make_ulonglong2((unsigned long long)a0, (unsigned long long)a1);
            *reinterpret_cast<ulonglong2*>(pp + 4) =
                make_ulonglong2((unsigned long long)a2, (unsigned long long)a3);
        }

        xraw[nxt * (INDIM * BT) + tid] = xv;

        __syncthreads();   // partials + xraw visible; hraw[cur] reads done

        if (tid == 0) {    // release hraw[cur] for refill
            #pragma unroll
            for (int p = 0; p < CLUSTER_G; p++)
                mbar_remote_arrive(empty_bar0 + cur * 8, (uint32_t)p);
        }

        if (tid < BT * JC) {
            const int jl = tid >> 2;
            const int b  = tid & 3;
            float s = 0.0f;
            #pragma unroll
            for (int w = 0; w < NWARPS; w++)
                s += part[w * (BT * JC) + tid];      // conflict-free: addr = tid*4B
            const float v = tanhf(s + bias[jl]);

            out[(size_t)t * BATCH * HDIM + (b0 + b) * HDIM + (j0 + jl)] = v;
            if (t == SEQ - 1)
                out[(size_t)SEQ * BATCH * HDIM + (b0 + b) * HDIM + (j0 + jl)] = v;

            stage[tid] = v;                          // [jl][b], 1KB slice
        }

        __syncthreads();   // stage complete

        if (t + 1 < SEQ && warp == 0 && lane < CLUSTER_G) {
            asm volatile("fence.proxy.async.shared::cta;" ::: "memory");
            mbar_wait_parity(empty_bar0 + nxt * 8, (uint32_t)((t >> 1) & 1));
            const uint32_t dst = hraw_base + (uint32_t)((nxt * HDIM * BT + j0 * BT) * 4);
            bulk_copy_to_peer(dst, stage_base, (uint32_t)(JC * BT * 4),
                              full_bar0 + nxt * 8, (uint32_t)lane);
        }
    }

    cluster_sync_all();
}

extern "C" void kernel_launch(void* const* d_in, const int* in_sizes, int n_in,
                              void* d_out, int out_size) {
    const float* x  = (const float*)d_in[0];
    const float* Wi = (const float*)d_in[1];
    const float* bi = (const float*)d_in[2];
    const float* Wh = (const float*)d_in[3];
    const float* bh = (const float*)d_in[4];
    float* out = (float*)d_out;

    cudaFuncSetAttribute(rnn_persistent_kernel,
                         cudaFuncAttributeMaxDynamicSharedMemorySize, SMEM_BYTES);

    rnn_persistent_kernel<<<(BATCH / BT) * CLUSTER_G, NTHREADS, SMEM_BYTES>>>(
        x, Wi, bi, Wh, bh, out);
}